// round 3
// baseline (speedup 1.0000x reference)
#include <cuda_runtime.h>
#include <cuda_bf16.h>
#include <math.h>

// ---------------------------------------------------------------------------
// DiscriminativeLoss: B=4 batches, two losses:
//   binary:   pred [2, N], labels in [0,2)
//   instance: pred [5, N], labels in [0,6)
// out[0] = mean_b binary_loss, out[1] = mean_b instance_loss
// ---------------------------------------------------------------------------

#define DELTA_V   0.5f
#define TWO_DD    6.0f     // 2 * delta_d
#define PREG      0.001f

// Scratch (alloc-free rule: __device__ globals). Zero-initialized at load;
// finalize_kernel re-zeros accumulators after each use so graph replays are
// deterministic.
__device__ float g_sum[2][4][8][8];   // [type][b][k][d]
__device__ float g_cnt[2][4][8];      // [type][b][k]
__device__ float g_var[2][4][8];      // [type][b][k]
__device__ float g_mean[2][4][8][8];  // [type][b][k][d]
__device__ float g_partial[2][4];     // dist + reg terms per (type,b)

// ---------------------------------------------------------------------------
// Pass 1: segment sums + counts
// ---------------------------------------------------------------------------
template <int D, int K>
__device__ __forceinline__ void reduce_impl(const float* __restrict__ pred,
                                            const int* __restrict__ labels,
                                            int N, float* __restrict__ gsum,
                                            float* __restrict__ gcnt) {
    float s[K * D];
    float c[K];
#pragma unroll
    for (int i = 0; i < K * D; i++) s[i] = 0.f;
#pragma unroll
    for (int k = 0; k < K; k++) c[k] = 0.f;

    const int n4 = N >> 2;
    const int4* lab4 = (const int4*)labels;
    const int stride = gridDim.x * blockDim.x;

    for (int i = blockIdx.x * blockDim.x + threadIdx.x; i < n4; i += stride) {
        int4 L = lab4[i];
        float4 v[D];
#pragma unroll
        for (int d = 0; d < D; d++)
            v[d] = ((const float4*)(pred + (size_t)d * N))[i];

        int ls[4] = {L.x, L.y, L.z, L.w};
#pragma unroll
        for (int e = 0; e < 4; e++) {
            int lab = ls[e];
#pragma unroll
            for (int k = 0; k < K; k++) {
                float m = (lab == k) ? 1.f : 0.f;
                c[k] += m;
#pragma unroll
                for (int d = 0; d < D; d++) {
                    float val = (e == 0) ? v[d].x : (e == 1) ? v[d].y
                               : (e == 2) ? v[d].z : v[d].w;
                    s[k * D + d] += m * val;
                }
            }
        }
    }

    // warp tree reduce
#pragma unroll
    for (int o = 16; o > 0; o >>= 1) {
#pragma unroll
        for (int i = 0; i < K * D; i++) s[i] += __shfl_xor_sync(0xffffffffu, s[i], o);
#pragma unroll
        for (int k = 0; k < K; k++) c[k] += __shfl_xor_sync(0xffffffffu, c[k], o);
    }

    __shared__ float sh[K * D + K];
    for (int i = threadIdx.x; i < K * D + K; i += blockDim.x) sh[i] = 0.f;
    __syncthreads();
    if ((threadIdx.x & 31) == 0) {
#pragma unroll
        for (int i = 0; i < K * D; i++) atomicAdd(&sh[i], s[i]);
#pragma unroll
        for (int k = 0; k < K; k++) atomicAdd(&sh[K * D + k], c[k]);
    }
    __syncthreads();
    if (threadIdx.x < K * D) {
        int k = threadIdx.x / D, d = threadIdx.x % D;
        atomicAdd(&gsum[k * 8 + d], sh[threadIdx.x]);
    }
    if (threadIdx.x < K) atomicAdd(&gcnt[threadIdx.x], sh[K * D + threadIdx.x]);
}

__global__ __launch_bounds__(256) void pass1_kernel(
    const float* __restrict__ binL, const int* __restrict__ binLab,
    const float* __restrict__ instL, const int* __restrict__ instLab, int N) {
    int b = blockIdx.y;
    if (blockIdx.z == 0) {
        reduce_impl<2, 2>(binL + (size_t)b * 2 * N, binLab + (size_t)b * N, N,
                          &g_sum[0][b][0][0], &g_cnt[0][b][0]);
    } else {
        reduce_impl<5, 6>(instL + (size_t)b * 5 * N, instLab + (size_t)b * N, N,
                          &g_sum[1][b][0][0], &g_cnt[1][b][0]);
    }
}

// ---------------------------------------------------------------------------
// Means + pairwise distance term + regularizer (tiny)
// ---------------------------------------------------------------------------
__global__ void means_kernel() {
    int t = threadIdx.x;
    if (t >= 8) return;
    int type = t >> 2, b = t & 3;
    int K = type ? 6 : 2, D = type ? 5 : 2;

    float m[6][5];
    for (int k = 0; k < K; k++) {
        float cnt = g_cnt[type][b][k];
        for (int d = 0; d < D; d++) {
            float mm = g_sum[type][b][k][d] / cnt;
            m[k][d] = mm;
            g_mean[type][b][k][d] = mm;
        }
    }
    float ld = 0.f;
    for (int i = 0; i < K; i++)
        for (int j = 0; j < K; j++) {
            if (i == j) continue;
            float sq = 0.f;
            for (int d = 0; d < D; d++) {
                float df = m[i][d] - m[j][d];
                sq += df * df;
            }
            float dn = fmaxf(TWO_DD - sqrtf(sq), 0.f);
            ld += dn * dn;
        }
    ld /= (float)(K * (K - 1));
    float lr = 0.f;
    for (int k = 0; k < K; k++) {
        float sq = 0.f;
        for (int d = 0; d < D; d++) sq += m[k][d] * m[k][d];
        lr += sqrtf(sq);
    }
    lr /= (float)K;
    g_partial[type][b] = ld + PREG * lr;
}

// ---------------------------------------------------------------------------
// Pass 2: variance (pull) term
// ---------------------------------------------------------------------------
template <int D, int K>
__device__ __forceinline__ void var_impl(const float* __restrict__ pred,
                                         const int* __restrict__ labels, int N,
                                         const float* __restrict__ gmean,
                                         float* __restrict__ gvar) {
    __shared__ float sm[K * D];
    if (threadIdx.x < K * D) {
        int k = threadIdx.x / D, d = threadIdx.x % D;
        sm[threadIdx.x] = gmean[k * 8 + d];
    }
    __syncthreads();

    float acc[K];
#pragma unroll
    for (int k = 0; k < K; k++) acc[k] = 0.f;

    const int n4 = N >> 2;
    const int4* lab4 = (const int4*)labels;
    const int stride = gridDim.x * blockDim.x;

    for (int i = blockIdx.x * blockDim.x + threadIdx.x; i < n4; i += stride) {
        int4 L = lab4[i];
        float4 v[D];
#pragma unroll
        for (int d = 0; d < D; d++)
            v[d] = ((const float4*)(pred + (size_t)d * N))[i];

        int ls[4] = {L.x, L.y, L.z, L.w};
#pragma unroll
        for (int e = 0; e < 4; e++) {
            int lab = ls[e];
            float sq = 0.f;
#pragma unroll
            for (int d = 0; d < D; d++) {
                float val = (e == 0) ? v[d].x : (e == 1) ? v[d].y
                           : (e == 2) ? v[d].z : v[d].w;
                float df = sm[lab * D + d] - val;
                sq += df * df;
            }
            float dist = sqrtf(sq);
            float h = fmaxf(dist - DELTA_V, 0.f);
            h = h * h;
#pragma unroll
            for (int k = 0; k < K; k++)
                acc[k] += (lab == k) ? h : 0.f;
        }
    }

#pragma unroll
    for (int o = 16; o > 0; o >>= 1) {
#pragma unroll
        for (int k = 0; k < K; k++) acc[k] += __shfl_xor_sync(0xffffffffu, acc[k], o);
    }

    __shared__ float shv[K];
    if (threadIdx.x < K) shv[threadIdx.x] = 0.f;
    __syncthreads();
    if ((threadIdx.x & 31) == 0) {
#pragma unroll
        for (int k = 0; k < K; k++) atomicAdd(&shv[k], acc[k]);
    }
    __syncthreads();
    if (threadIdx.x < K) atomicAdd(&gvar[threadIdx.x], shv[threadIdx.x]);
}

__global__ __launch_bounds__(256) void pass2_kernel(
    const float* __restrict__ binL, const int* __restrict__ binLab,
    const float* __restrict__ instL, const int* __restrict__ instLab, int N) {
    int b = blockIdx.y;
    if (blockIdx.z == 0) {
        var_impl<2, 2>(binL + (size_t)b * 2 * N, binLab + (size_t)b * N, N,
                       &g_mean[0][b][0][0], &g_var[0][b][0]);
    } else {
        var_impl<5, 6>(instL + (size_t)b * 5 * N, instLab + (size_t)b * N, N,
                       &g_mean[1][b][0][0], &g_var[1][b][0]);
    }
}

// ---------------------------------------------------------------------------
// Finalize: combine terms, write 2 floats, re-zero accumulators for replay.
// ---------------------------------------------------------------------------
__global__ void finalize_kernel(float* __restrict__ out) {
    if (threadIdx.x == 0) {
        float res[2];
        for (int type = 0; type < 2; type++) {
            int K = type ? 6 : 2;
            float tot = 0.f;
            for (int b = 0; b < 4; b++) {
                float lv = 0.f;
                for (int k = 0; k < K; k++)
                    lv += g_var[type][b][k] / g_cnt[type][b][k];
                lv /= (float)K;
                tot += g_partial[type][b] + lv;
            }
            res[type] = tot * 0.25f;
        }
        out[0] = res[0];
        out[1] = res[1];
    }
    __syncthreads();  // thread 0 done reading before anyone zeroes
    float* p1 = &g_sum[0][0][0][0];
    for (int i = threadIdx.x; i < 2 * 4 * 8 * 8; i += blockDim.x) p1[i] = 0.f;
    float* p2 = &g_cnt[0][0][0];
    for (int i = threadIdx.x; i < 2 * 4 * 8; i += blockDim.x) p2[i] = 0.f;
    float* p3 = &g_var[0][0][0];
    for (int i = threadIdx.x; i < 2 * 4 * 8; i += blockDim.x) p3[i] = 0.f;
}

// ---------------------------------------------------------------------------
extern "C" void kernel_launch(void* const* d_in, const int* in_sizes, int n_in,
                              void* d_out, int out_size) {
    const float* binL    = (const float*)d_in[0];
    const int*   binLab  = (const int*)d_in[1];
    const float* instL   = (const float*)d_in[2];
    const int*   instLab = (const int*)d_in[3];
    float* out = (float*)d_out;

    int N = in_sizes[1] / 4;  // B = 4 batches

    dim3 grid(128, 4, 2);
    pass1_kernel<<<grid, 256>>>(binL, binLab, instL, instLab, N);
    means_kernel<<<1, 32>>>();
    pass2_kernel<<<grid, 256>>>(binL, binLab, instL, instLab, N);
    finalize_kernel<<<1, 256>>>(out);
}

// round 4
// speedup vs baseline: 1.0968x; 1.0968x over previous
#include <cuda_runtime.h>
#include <cuda_bf16.h>
#include <math.h>

// ---------------------------------------------------------------------------
// DiscriminativeLoss: B=4 batches, two losses:
//   binary:   pred [2, N], labels in [0,2)
//   instance: pred [5, N], labels in [0,6)
// out[0] = mean_b binary_loss, out[1] = mean_b instance_loss
//
// 2 kernels: pass1 (segment sums/counts), pass2 (means in prologue, hinge
// variance accumulation, last-block finalize + scratch re-zero).
// ---------------------------------------------------------------------------

#define DELTA_V   0.5f
#define TWO_DD    6.0f     // 2 * delta_d
#define PREG      0.001f

#define GRID_X    128
#define TOTAL_BLOCKS (GRID_X * 4 * 2)

// Scratch (alloc-free rule: __device__ globals). Zero at load; the pass2
// last block re-zeros everything so graph replays are deterministic.
__device__ float    g_sum[2][4][8][8];   // [type][b][k][d]
__device__ float    g_cnt[2][4][8];      // [type][b][k]
__device__ float    g_var[2][4][8];      // [type][b][k]
__device__ unsigned g_done;

// ---------------------------------------------------------------------------
// Pass 1: segment sums + counts
// ---------------------------------------------------------------------------
template <int D, int K>
__device__ __forceinline__ void reduce_impl(const float* __restrict__ pred,
                                            const int* __restrict__ labels,
                                            int N, float* __restrict__ gsum,
                                            float* __restrict__ gcnt) {
    float s[K * D];
    float c[K];
#pragma unroll
    for (int i = 0; i < K * D; i++) s[i] = 0.f;
#pragma unroll
    for (int k = 0; k < K; k++) c[k] = 0.f;

    const int n4 = N >> 2;
    const int4* lab4 = (const int4*)labels;
    const int stride = gridDim.x * blockDim.x;

    for (int i = blockIdx.x * blockDim.x + threadIdx.x; i < n4; i += stride) {
        int4 L = lab4[i];
        float4 v[D];
#pragma unroll
        for (int d = 0; d < D; d++)
            v[d] = ((const float4*)(pred + (size_t)d * N))[i];

        int ls[4] = {L.x, L.y, L.z, L.w};
#pragma unroll
        for (int e = 0; e < 4; e++) {
            int lab = ls[e];
#pragma unroll
            for (int k = 0; k < K; k++) {
                float m = (lab == k) ? 1.f : 0.f;
                c[k] += m;
#pragma unroll
                for (int d = 0; d < D; d++) {
                    float val = (e == 0) ? v[d].x : (e == 1) ? v[d].y
                               : (e == 2) ? v[d].z : v[d].w;
                    s[k * D + d] += m * val;
                }
            }
        }
    }

#pragma unroll
    for (int o = 16; o > 0; o >>= 1) {
#pragma unroll
        for (int i = 0; i < K * D; i++) s[i] += __shfl_xor_sync(0xffffffffu, s[i], o);
#pragma unroll
        for (int k = 0; k < K; k++) c[k] += __shfl_xor_sync(0xffffffffu, c[k], o);
    }

    __shared__ float sh[K * D + K];
    for (int i = threadIdx.x; i < K * D + K; i += blockDim.x) sh[i] = 0.f;
    __syncthreads();
    if ((threadIdx.x & 31) == 0) {
#pragma unroll
        for (int i = 0; i < K * D; i++) atomicAdd(&sh[i], s[i]);
#pragma unroll
        for (int k = 0; k < K; k++) atomicAdd(&sh[K * D + k], c[k]);
    }
    __syncthreads();
    if (threadIdx.x < K * D) {
        int k = threadIdx.x / D, d = threadIdx.x % D;
        atomicAdd(&gsum[k * 8 + d], sh[threadIdx.x]);
    }
    if (threadIdx.x < K) atomicAdd(&gcnt[threadIdx.x], sh[K * D + threadIdx.x]);
}

__global__ __launch_bounds__(256) void pass1_kernel(
    const float* __restrict__ binL, const int* __restrict__ binLab,
    const float* __restrict__ instL, const int* __restrict__ instLab, int N) {
    int b = blockIdx.y;
    if (blockIdx.z == 0) {
        reduce_impl<2, 2>(binL + (size_t)b * 2 * N, binLab + (size_t)b * N, N,
                          &g_sum[0][b][0][0], &g_cnt[0][b][0]);
    } else {
        reduce_impl<5, 6>(instL + (size_t)b * 5 * N, instLab + (size_t)b * N, N,
                          &g_sum[1][b][0][0], &g_cnt[1][b][0]);
    }
}

// ---------------------------------------------------------------------------
// Pass 2: per-block means prologue, hinge-variance accumulation,
// last-block finalize (dist + reg + var combine) and scratch re-zero.
// ---------------------------------------------------------------------------
template <int D, int K>
__device__ __forceinline__ void var_impl(const float* __restrict__ pred,
                                         const int* __restrict__ labels, int N,
                                         const float* __restrict__ gsum,
                                         const float* __restrict__ gcnt,
                                         float* __restrict__ gvar) {
    // Prologue: compute segment means from pass1 results (≈K*D L2 loads).
    __shared__ float sm[K * D];
    if (threadIdx.x < K * D) {
        int k = threadIdx.x / D, d = threadIdx.x % D;
        sm[threadIdx.x] = gsum[k * 8 + d] / gcnt[k];
    }
    __syncthreads();

    float acc[K];
#pragma unroll
    for (int k = 0; k < K; k++) acc[k] = 0.f;

    const int n4 = N >> 2;
    const int4* lab4 = (const int4*)labels;
    const int stride = gridDim.x * blockDim.x;

    for (int i = blockIdx.x * blockDim.x + threadIdx.x; i < n4; i += stride) {
        int4 L = lab4[i];
        float4 v[D];
#pragma unroll
        for (int d = 0; d < D; d++)
            v[d] = ((const float4*)(pred + (size_t)d * N))[i];

        int ls[4] = {L.x, L.y, L.z, L.w};
#pragma unroll
        for (int e = 0; e < 4; e++) {
            int lab = ls[e];
            float sq = 0.f;
#pragma unroll
            for (int d = 0; d < D; d++) {
                float val = (e == 0) ? v[d].x : (e == 1) ? v[d].y
                           : (e == 2) ? v[d].z : v[d].w;
                float df = sm[lab * D + d] - val;
                sq += df * df;
            }
            float dist = sqrtf(sq);
            float h = fmaxf(dist - DELTA_V, 0.f);
            h = h * h;
#pragma unroll
            for (int k = 0; k < K; k++)
                acc[k] += (lab == k) ? h : 0.f;
        }
    }

#pragma unroll
    for (int o = 16; o > 0; o >>= 1) {
#pragma unroll
        for (int k = 0; k < K; k++) acc[k] += __shfl_xor_sync(0xffffffffu, acc[k], o);
    }

    __shared__ float shv[K];
    if (threadIdx.x < K) shv[threadIdx.x] = 0.f;
    __syncthreads();
    if ((threadIdx.x & 31) == 0) {
#pragma unroll
        for (int k = 0; k < K; k++) atomicAdd(&shv[k], acc[k]);
    }
    __syncthreads();
    if (threadIdx.x < K) atomicAdd(&gvar[threadIdx.x], shv[threadIdx.x]);
}

__global__ __launch_bounds__(256) void pass2_kernel(
    const float* __restrict__ binL, const int* __restrict__ binLab,
    const float* __restrict__ instL, const int* __restrict__ instLab, int N,
    float* __restrict__ out) {
    int b = blockIdx.y;
    if (blockIdx.z == 0) {
        var_impl<2, 2>(binL + (size_t)b * 2 * N, binLab + (size_t)b * N, N,
                       &g_sum[0][b][0][0], &g_cnt[0][b][0], &g_var[0][b][0]);
    } else {
        var_impl<5, 6>(instL + (size_t)b * 5 * N, instLab + (size_t)b * N, N,
                       &g_sum[1][b][0][0], &g_cnt[1][b][0], &g_var[1][b][0]);
    }

    // ---- last-block finalize ----
    __threadfence();            // order this block's g_var atomics
    __syncthreads();
    __shared__ bool is_last;
    if (threadIdx.x == 0) {
        unsigned v = atomicAdd(&g_done, 1u);
        is_last = (v == (unsigned)(TOTAL_BLOCKS - 1));
    }
    __syncthreads();
    if (!is_last) return;
    __threadfence();            // acquire: see all blocks' g_var/g_sum/g_cnt

    __shared__ float s_res[2];
    if (threadIdx.x < 8) {
        int type = threadIdx.x >> 2, b2 = threadIdx.x & 3;
        int K = type ? 6 : 2, D = type ? 5 : 2;

        float m[6][5];
        float l_var = 0.f;
        for (int k = 0; k < K; k++) {
            float cnt = g_cnt[type][b2][k];
            for (int d = 0; d < D; d++)
                m[k][d] = g_sum[type][b2][k][d] / cnt;
            l_var += g_var[type][b2][k] / cnt;
        }
        l_var /= (float)K;

        float ld = 0.f;
        for (int i = 0; i < K; i++)
            for (int j = 0; j < K; j++) {
                if (i == j) continue;
                float sq = 0.f;
                for (int d = 0; d < D; d++) {
                    float df = m[i][d] - m[j][d];
                    sq += df * df;
                }
                float dn = fmaxf(TWO_DD - sqrtf(sq), 0.f);
                ld += dn * dn;
            }
        ld /= (float)(K * (K - 1));

        float lr = 0.f;
        for (int k = 0; k < K; k++) {
            float sq = 0.f;
            for (int d = 0; d < D; d++) sq += m[k][d] * m[k][d];
            lr += sqrtf(sq);
        }
        lr /= (float)K;

        float loss = l_var + ld + PREG * lr;
        // sum the 4 batches within each type via shuffles (lanes 0-3, 4-7)
        loss += __shfl_xor_sync(0x000000ffu, loss, 1);
        loss += __shfl_xor_sync(0x000000ffu, loss, 2);
        if ((threadIdx.x & 3) == 0) s_res[type] = loss * 0.25f;
    }
    __syncthreads();
    if (threadIdx.x == 0) {
        out[0] = s_res[0];
        out[1] = s_res[1];
        g_done = 0;
    }
    // re-zero accumulators for the next graph replay
    float* p1 = &g_sum[0][0][0][0];
    for (int i = threadIdx.x; i < 2 * 4 * 8 * 8; i += blockDim.x) p1[i] = 0.f;
    float* p2 = &g_cnt[0][0][0];
    for (int i = threadIdx.x; i < 2 * 4 * 8; i += blockDim.x) p2[i] = 0.f;
    float* p3 = &g_var[0][0][0];
    for (int i = threadIdx.x; i < 2 * 4 * 8; i += blockDim.x) p3[i] = 0.f;
}

// ---------------------------------------------------------------------------
extern "C" void kernel_launch(void* const* d_in, const int* in_sizes, int n_in,
                              void* d_out, int out_size) {
    const float* binL    = (const float*)d_in[0];
    const int*   binLab  = (const int*)d_in[1];
    const float* instL   = (const float*)d_in[2];
    const int*   instLab = (const int*)d_in[3];
    float* out = (float*)d_out;

    int N = in_sizes[1] / 4;  // B = 4 batches

    dim3 grid(GRID_X, 4, 2);
    pass1_kernel<<<grid, 256>>>(binL, binLab, instL, instLab, N);
    pass2_kernel<<<grid, 256>>>(binL, binLab, instL, instLab, N, out);
}